// round 5
// baseline (speedup 1.0000x reference)
#include <cuda_runtime.h>

// Problem dimensions (fixed by the reference setup)
#define BB 4
#define LL 4096
#define DD 128
#define NN 16
#define TT 64               // chunk length
#define NC (LL / TT)        // 64 chunks per batch
#define DT_OFF 0.1f

// Scratch (device globals — no allocation allowed)
__device__ __align__(16) float g_coef[BB * LL * 48];      // [b][l][e0..15,w0..15,C0..15]
__device__ __align__(16) float g_E[BB * NC * DD * NN];    // chunk-local end states
__device__ __align__(16) float g_H0[BB * NC * DD * NN];   // carry-in state per chunk
__device__ float g_P[BB * NC * NN];                        // chunk decay products

// ---------------------------------------------------------------------------
// K1: per-(b,l) coefficients.  33 dot products of length 128 per position:
//   Bp[n] = x·Wb[n] + bb[n],  C[n] = x·Wc[n] + bc[n],  z = x·Wd + bd
//   delta = softplus(z) + 0.1
//   e[n]  = exp(delta*A[n]);  w[n] = (1 - exp(-delta*A[n])) * delta * Bp[n]
// Two threads per position (split the 128-dim dot), combined via shfl.
// ---------------------------------------------------------------------------
__global__ __launch_bounds__(128) void k1_coef(
    const float* __restrict__ x,
    const float* __restrict__ A,
    const float* __restrict__ Wb, const float* __restrict__ bb,
    const float* __restrict__ Wc, const float* __restrict__ bc,
    const float* __restrict__ Wd, const float* __restrict__ bd)
{
    __shared__ __align__(16) float sW[33 * 128];
    __shared__ float sb[33];
    __shared__ float sA[16];

    int tid = threadIdx.x;
    for (int i = tid; i < 2048; i += 128) {
        sW[i]        = Wb[i];
        sW[2048 + i] = Wc[i];
    }
    sW[4096 + tid] = Wd[tid];
    if (tid < 16) { sb[tid] = bb[tid]; sb[16 + tid] = bc[tid]; sA[tid] = A[tid]; }
    if (tid == 0) sb[32] = bd[0];
    __syncthreads();

    int g    = blockIdx.x * 128 + tid;       // 0..32767
    int pos  = g >> 1;                        // (b*L + l)
    int half = g & 1;                         // which 64-dim half of the dot

    float acc[33];
#pragma unroll
    for (int j = 0; j < 33; j++) acc[j] = 0.f;

    const float4* xr = (const float4*)(x + (size_t)pos * DD + half * 64);
    const float4* W4 = (const float4*)sW;

#pragma unroll
    for (int kk = 0; kk < 16; kk++) {
        float4 xv = xr[kk];
        int basei = half * 16 + kk;
#pragma unroll
        for (int j = 0; j < 33; j++) {
            float4 wv = W4[j * 32 + basei];
            acc[j] = fmaf(xv.w, wv.w, fmaf(xv.z, wv.z,
                     fmaf(xv.y, wv.y, fmaf(xv.x, wv.x, acc[j]))));
        }
    }
#pragma unroll
    for (int j = 0; j < 33; j++)
        acc[j] += __shfl_down_sync(0xffffffffu, acc[j], 1);

    if (half == 0) {
        float z = acc[32] + sb[32];
        // stable softplus matching jax.nn.softplus
        float delta = fmaxf(z, 0.f) + log1pf(expf(-fabsf(z))) + DT_OFF;

        float out[48];
#pragma unroll
        for (int n = 0; n < 16; n++) {
            float da = delta * sA[n];
            out[n]      = expf(da);
            out[16 + n] = (1.0f - expf(-da)) * delta * (acc[n] + sb[n]);
            out[32 + n] = acc[16 + n] + sb[16 + n];
        }
        float4* o = (float4*)(g_coef + (size_t)pos * 48);
        const float4* ov = (const float4*)out;
#pragma unroll
        for (int i = 0; i < 12; i++) o[i] = ov[i];
    }
}

// ---------------------------------------------------------------------------
// K2: chunk-local scan with h=0 init.  Block = (chunk c, batch b), thread = d.
// Stores end state E[b,c,d,:] and decay product P[b,c,:].
// ---------------------------------------------------------------------------
__global__ __launch_bounds__(128) void k2_local(const float* __restrict__ x)
{
    __shared__ __align__(16) float sc[TT * 48];
    int c = blockIdx.x, b = blockIdx.y, d = threadIdx.x;

    const float4* src = (const float4*)(g_coef + (size_t)(b * LL + c * TT) * 48);
    float4* dst = (float4*)sc;
#pragma unroll
    for (int i = 0; i < 6; i++) dst[d + 128 * i] = src[d + 128 * i];
    __syncthreads();

    float h[16];
#pragma unroll
    for (int n = 0; n < 16; n++) h[n] = 0.f;

    const float* xp = x + (size_t)(b * LL + c * TT) * DD + d;

#pragma unroll 4
    for (int t = 0; t < TT; t++) {
        float xt = xp[t * DD];
        const float4* row = (const float4*)(sc + t * 48);
        float4 E4[4], W4[4];
#pragma unroll
        for (int i = 0; i < 4; i++) { E4[i] = row[i]; W4[i] = row[4 + i]; }
        const float* ee = (const float*)E4;
        const float* ww = (const float*)W4;
#pragma unroll
        for (int n = 0; n < 16; n++) h[n] = fmaf(ee[n], h[n], ww[n] * xt);
    }

    float4* Eo = (float4*)(g_E + (size_t)((b * NC + c) * DD + d) * NN);
    const float4* hv = (const float4*)h;
#pragma unroll
    for (int i = 0; i < 4; i++) Eo[i] = hv[i];

    if (d < 16) {
        float p = 1.f;
        for (int t = 0; t < TT; t++) p *= sc[t * 48 + d];
        g_P[(b * NC + c) * NN + d] = p;
    }
}

// ---------------------------------------------------------------------------
// K2.5: inter-chunk combine.  One thread per (b,d,n); sequential over chunks:
//   H0[c] = h;  h = P[c]*h + E[c]
// ---------------------------------------------------------------------------
__global__ void k25_combine()
{
    int idx = blockIdx.x * blockDim.x + threadIdx.x;  // 0..8191
    int b = idx >> 11;          // / (D*N)
    int r = idx & 2047;         // d*16 + n
    int n = r & 15;
    float h = 0.f;
#pragma unroll 4
    for (int c = 0; c < NC; c++) {
        size_t o = (size_t)(b * NC + c) * (DD * NN) + r;
        g_H0[o] = h;
        h = fmaf(g_P[(b * NC + c) * NN + n], h, g_E[o]);
    }
}

// ---------------------------------------------------------------------------
// K3: final scan with carry-in, emits y[b,l,d] = sum_n C[l,n]*h[n].
// ---------------------------------------------------------------------------
__global__ __launch_bounds__(128) void k3_scan(const float* __restrict__ x,
                                               float* __restrict__ y)
{
    __shared__ __align__(16) float sc[TT * 48];
    int c = blockIdx.x, b = blockIdx.y, d = threadIdx.x;

    const float4* src = (const float4*)(g_coef + (size_t)(b * LL + c * TT) * 48);
    float4* dst = (float4*)sc;
#pragma unroll
    for (int i = 0; i < 6; i++) dst[d + 128 * i] = src[d + 128 * i];

    float h[16];
    const float4* hi = (const float4*)(g_H0 + (size_t)((b * NC + c) * DD + d) * NN);
    float4* hv = (float4*)h;
#pragma unroll
    for (int i = 0; i < 4; i++) hv[i] = hi[i];
    __syncthreads();

    const float* xp = x + (size_t)(b * LL + c * TT) * DD + d;
    float*       yp = y + (size_t)(b * LL + c * TT) * DD + d;

#pragma unroll 4
    for (int t = 0; t < TT; t++) {
        float xt = xp[t * DD];
        const float4* row = (const float4*)(sc + t * 48);
        float4 E4[4], W4[4], C4[4];
#pragma unroll
        for (int i = 0; i < 4; i++) { E4[i] = row[i]; W4[i] = row[4 + i]; C4[i] = row[8 + i]; }
        const float* ee = (const float*)E4;
        const float* ww = (const float*)W4;
        const float* cc = (const float*)C4;
#pragma unroll
        for (int n = 0; n < 16; n++) h[n] = fmaf(ee[n], h[n], ww[n] * xt);

        float ys[4] = {0.f, 0.f, 0.f, 0.f};
#pragma unroll
        for (int n = 0; n < 16; n++) ys[n & 3] = fmaf(cc[n], h[n], ys[n & 3]);
        yp[t * DD] = (ys[0] + ys[1]) + (ys[2] + ys[3]);
    }
}

// ---------------------------------------------------------------------------
extern "C" void kernel_launch(void* const* d_in, const int* in_sizes, int n_in,
                              void* d_out, int out_size)
{
    const float* x  = (const float*)d_in[0];
    const float* A  = (const float*)d_in[1];
    const float* Wb = (const float*)d_in[2];
    const float* bb = (const float*)d_in[3];
    const float* Wc = (const float*)d_in[4];
    const float* bc = (const float*)d_in[5];
    const float* Wd = (const float*)d_in[6];
    const float* bd = (const float*)d_in[7];
    float* y = (float*)d_out;

    // K1: 2 threads per (b,l) position -> 32768 threads
    k1_coef<<<256, 128>>>(x, A, Wb, bb, Wc, bc, Wd, bd);

    dim3 grid(NC, BB);
    k2_local<<<grid, 128>>>(x);
    k25_combine<<<32, 256>>>();
    k3_scan<<<grid, 128>>>(x, y);
}

// round 6
// speedup vs baseline: 1.0086x; 1.0086x over previous
#include <cuda_runtime.h>

// Problem dimensions (fixed by the reference setup)
#define BB 4
#define LL 4096
#define DD 128
#define NN 16
#define TT 64               // chunk length
#define NC (LL / TT)        // 64 chunks per batch
#define DT_OFF 0.1f

// Scratch (device globals — no allocation allowed)
__device__ __align__(16) float g_coef[BB * LL * 48];      // [b][l][e0..15,w0..15,C0..15]
__device__ __align__(16) float g_E[BB * NC * DD * NN];    // chunk-local end states
__device__ __align__(16) float g_H0[BB * NC * DD * NN];   // carry-in state per chunk
__device__ float g_P[BB * NC * NN];                        // chunk decay products

// ---------------------------------------------------------------------------
// K1: per-(b,l) coefficients.  33 dot products of length 128 per position:
//   Bp[n] = x·Wb[n] + bb[n],  C[n] = x·Wc[n] + bc[n],  z = x·Wd + bd
//   delta = softplus(z) + 0.1
//   e[n]  = exp(delta*A[n]);  w[n] = (1 - exp(-delta*A[n])) * delta * Bp[n]
// Two threads per position (split the 128-dim dot), combined via shfl.
// ---------------------------------------------------------------------------
__global__ __launch_bounds__(128) void k1_coef(
    const float* __restrict__ x,
    const float* __restrict__ A,
    const float* __restrict__ Wb, const float* __restrict__ bb,
    const float* __restrict__ Wc, const float* __restrict__ bc,
    const float* __restrict__ Wd, const float* __restrict__ bd)
{
    __shared__ __align__(16) float sW[33 * 128];
    __shared__ float sb[33];
    __shared__ float sA[16];

    int tid = threadIdx.x;
    for (int i = tid; i < 2048; i += 128) {
        sW[i]        = Wb[i];
        sW[2048 + i] = Wc[i];
    }
    sW[4096 + tid] = Wd[tid];
    if (tid < 16) { sb[tid] = bb[tid]; sb[16 + tid] = bc[tid]; sA[tid] = A[tid]; }
    if (tid == 0) sb[32] = bd[0];
    __syncthreads();

    int g    = blockIdx.x * 128 + tid;       // 0..32767
    int pos  = g >> 1;                        // (b*L + l)
    int half = g & 1;                         // which 64-dim half of the dot

    float acc[33];
#pragma unroll
    for (int j = 0; j < 33; j++) acc[j] = 0.f;

    const float4* xr = (const float4*)(x + (size_t)pos * DD + half * 64);
    const float4* W4 = (const float4*)sW;

#pragma unroll
    for (int kk = 0; kk < 16; kk++) {
        float4 xv = xr[kk];
        int basei = half * 16 + kk;
#pragma unroll
        for (int j = 0; j < 33; j++) {
            float4 wv = W4[j * 32 + basei];
            acc[j] = fmaf(xv.w, wv.w, fmaf(xv.z, wv.z,
                     fmaf(xv.y, wv.y, fmaf(xv.x, wv.x, acc[j]))));
        }
    }
#pragma unroll
    for (int j = 0; j < 33; j++)
        acc[j] += __shfl_down_sync(0xffffffffu, acc[j], 1);

    if (half == 0) {
        float z = acc[32] + sb[32];
        // stable softplus matching jax.nn.softplus
        float delta = fmaxf(z, 0.f) + log1pf(expf(-fabsf(z))) + DT_OFF;

        float out[48];
#pragma unroll
        for (int n = 0; n < 16; n++) {
            float da = delta * sA[n];
            out[n]      = expf(da);
            out[16 + n] = (1.0f - expf(-da)) * delta * (acc[n] + sb[n]);
            out[32 + n] = acc[16 + n] + sb[16 + n];
        }
        float4* o = (float4*)(g_coef + (size_t)pos * 48);
        const float4* ov = (const float4*)out;
#pragma unroll
        for (int i = 0; i < 12; i++) o[i] = ov[i];
    }
}

// ---------------------------------------------------------------------------
// K2: chunk-local scan with h=0 init.  Block = (chunk c, batch b), thread = d.
// Stores end state E[b,c,d,:] and decay product P[b,c,:].
// ---------------------------------------------------------------------------
__global__ __launch_bounds__(128) void k2_local(const float* __restrict__ x)
{
    __shared__ __align__(16) float sc[TT * 48];
    int c = blockIdx.x, b = blockIdx.y, d = threadIdx.x;

    const float4* src = (const float4*)(g_coef + (size_t)(b * LL + c * TT) * 48);
    float4* dst = (float4*)sc;
#pragma unroll
    for (int i = 0; i < 6; i++) dst[d + 128 * i] = src[d + 128 * i];
    __syncthreads();

    float h[16];
#pragma unroll
    for (int n = 0; n < 16; n++) h[n] = 0.f;

    const float* xp = x + (size_t)(b * LL + c * TT) * DD + d;

#pragma unroll 4
    for (int t = 0; t < TT; t++) {
        float xt = xp[t * DD];
        const float4* row = (const float4*)(sc + t * 48);
        float4 E4[4], W4[4];
#pragma unroll
        for (int i = 0; i < 4; i++) { E4[i] = row[i]; W4[i] = row[4 + i]; }
        const float* ee = (const float*)E4;
        const float* ww = (const float*)W4;
#pragma unroll
        for (int n = 0; n < 16; n++) h[n] = fmaf(ee[n], h[n], ww[n] * xt);
    }

    float4* Eo = (float4*)(g_E + (size_t)((b * NC + c) * DD + d) * NN);
    const float4* hv = (const float4*)h;
#pragma unroll
    for (int i = 0; i < 4; i++) Eo[i] = hv[i];

    if (d < 16) {
        float p = 1.f;
        for (int t = 0; t < TT; t++) p *= sc[t * 48 + d];
        g_P[(b * NC + c) * NN + d] = p;
    }
}

// ---------------------------------------------------------------------------
// K2.5: inter-chunk combine.  One thread per (b,d,n); sequential over chunks:
//   H0[c] = h;  h = P[c]*h + E[c]
// ---------------------------------------------------------------------------
__global__ void k25_combine()
{
    int idx = blockIdx.x * blockDim.x + threadIdx.x;  // 0..8191
    int b = idx >> 11;          // / (D*N)
    int r = idx & 2047;         // d*16 + n
    int n = r & 15;
    float h = 0.f;
#pragma unroll 4
    for (int c = 0; c < NC; c++) {
        size_t o = (size_t)(b * NC + c) * (DD * NN) + r;
        g_H0[o] = h;
        h = fmaf(g_P[(b * NC + c) * NN + n], h, g_E[o]);
    }
}

// ---------------------------------------------------------------------------
// K3: final scan with carry-in, emits y[b,l,d] = sum_n C[l,n]*h[n].
// ---------------------------------------------------------------------------
__global__ __launch_bounds__(128) void k3_scan(const float* __restrict__ x,
                                               float* __restrict__ y)
{
    __shared__ __align__(16) float sc[TT * 48];
    int c = blockIdx.x, b = blockIdx.y, d = threadIdx.x;

    const float4* src = (const float4*)(g_coef + (size_t)(b * LL + c * TT) * 48);
    float4* dst = (float4*)sc;
#pragma unroll
    for (int i = 0; i < 6; i++) dst[d + 128 * i] = src[d + 128 * i];

    float h[16];
    const float4* hi = (const float4*)(g_H0 + (size_t)((b * NC + c) * DD + d) * NN);
    float4* hv = (float4*)h;
#pragma unroll
    for (int i = 0; i < 4; i++) hv[i] = hi[i];
    __syncthreads();

    const float* xp = x + (size_t)(b * LL + c * TT) * DD + d;
    float*       yp = y + (size_t)(b * LL + c * TT) * DD + d;

#pragma unroll 4
    for (int t = 0; t < TT; t++) {
        float xt = xp[t * DD];
        const float4* row = (const float4*)(sc + t * 48);
        float4 E4[4], W4[4], C4[4];
#pragma unroll
        for (int i = 0; i < 4; i++) { E4[i] = row[i]; W4[i] = row[4 + i]; C4[i] = row[8 + i]; }
        const float* ee = (const float*)E4;
        const float* ww = (const float*)W4;
        const float* cc = (const float*)C4;
#pragma unroll
        for (int n = 0; n < 16; n++) h[n] = fmaf(ee[n], h[n], ww[n] * xt);

        float ys[4] = {0.f, 0.f, 0.f, 0.f};
#pragma unroll
        for (int n = 0; n < 16; n++) ys[n & 3] = fmaf(cc[n], h[n], ys[n & 3]);
        yp[t * DD] = (ys[0] + ys[1]) + (ys[2] + ys[3]);
    }
}

// ---------------------------------------------------------------------------
extern "C" void kernel_launch(void* const* d_in, const int* in_sizes, int n_in,
                              void* d_out, int out_size)
{
    const float* x  = (const float*)d_in[0];
    const float* A  = (const float*)d_in[1];
    const float* Wb = (const float*)d_in[2];
    const float* bb = (const float*)d_in[3];
    const float* Wc = (const float*)d_in[4];
    const float* bc = (const float*)d_in[5];
    const float* Wd = (const float*)d_in[6];
    const float* bd = (const float*)d_in[7];
    float* y = (float*)d_out;

    // K1: 2 threads per (b,l) position -> 32768 threads
    k1_coef<<<256, 128>>>(x, A, Wb, bb, Wc, bc, Wd, bd);

    dim3 grid(NC, BB);
    k2_local<<<grid, 128>>>(x);
    k25_combine<<<32, 256>>>();
    k3_scan<<<grid, 128>>>(x, y);
}